// round 10
// baseline (speedup 1.0000x reference)
#include <cuda_runtime.h>
#include <cuda_bf16.h>
#include <cstdint>

// Problem dims
#define BATCH 256
#define SEQ   512
#define DIM   256
#define HID   1024
#define NCLS  10
#define NSTEP 511   // SEQ - 1
#define VOC   512

// Step GEMM tiling
#define MT  64            // batch tile
#define NT  64            // j tile (per gate; CTA computes g and i => 128 output cols)
#define KCH 64            // K chunk (64 bf16 = 128 B rows)
#define NCHUNK (HID / KCH)   // 16

// smem stage layout (byte offsets inside one stage)
#define ST_A_HI 0
#define ST_A_LO 8192
#define ST_B_HI 16384
#define ST_B_LO 32768
#define STAGE   49152
#define NSTAGE  3
#define OPITCH  132          // fp32 O tile row pitch (floats); 132*4=528 B, 16B-divisible

// -------- device scratch (no allocations allowed) --------
__device__ float g_P[2][VOC][2 * HID];                 // input projections, 8 MB
// transposed+split recurrent weights, gates merged on N: n<1024 -> g, n>=1024 -> i
__device__ __nv_bfloat16 g_Wt[2][2][2048][HID];        // [dir][hi/lo][n][k], 16 MB
__device__ __nv_bfloat16 g_hh[2][2][BATCH][HID];       // h high half [parity][dir][b][k]
__device__ __nv_bfloat16 g_hl[2][2][BATCH][HID];       // h low  half
__device__ float g_c[2][BATCH][HID];                   // cell state fp32

// ==================== PTX helpers (baseline sm_80+ features only) ====================
__device__ __forceinline__ uint32_t smem_u32(const void* p) {
    uint32_t a;
    asm("{ .reg .u64 t; cvta.to.shared.u64 t, %1; cvt.u32.u64 %0, t; }" : "=r"(a) : "l"(p));
    return a;
}
__device__ __forceinline__ void cp16(uint32_t saddr, const void* g) {
    asm volatile("cp.async.cg.shared.global [%0], [%1], 16;" :: "r"(saddr), "l"(g) : "memory");
}
#define CP_COMMIT() asm volatile("cp.async.commit_group;" ::: "memory")
#define CP_WAIT2()  asm volatile("cp.async.wait_group 2;" ::: "memory")

__device__ __forceinline__ void ldm4(uint32_t* r, uint32_t addr) {
    asm volatile("ldmatrix.sync.aligned.m8n8.x4.shared.b16 {%0,%1,%2,%3}, [%4];"
                 : "=r"(r[0]), "=r"(r[1]), "=r"(r[2]), "=r"(r[3]) : "r"(addr));
}
// D(16x8,f32) += A(16x16 row-major bf16) * B(16x8 col-major bf16)
__device__ __forceinline__ void mma_bf16(float* c, const uint32_t* a, const uint32_t* b) {
    asm volatile("mma.sync.aligned.m16n8k16.row.col.f32.bf16.bf16.f32 "
                 "{%0,%1,%2,%3}, {%4,%5,%6,%7}, {%8,%9}, {%0,%1,%2,%3};"
                 : "+f"(c[0]), "+f"(c[1]), "+f"(c[2]), "+f"(c[3])
                 : "r"(a[0]), "r"(a[1]), "r"(a[2]), "r"(a[3]), "r"(b[0]), "r"(b[1]));
}
__device__ __forceinline__ float sigmoidf_(float x) { return 1.0f / (1.0f + __expf(-x)); }

// ==================== kernel 1: zero state ====================
__global__ void zero_state_kernel() {
    int i = blockIdx.x * blockDim.x + threadIdx.x;
    const int N = 2 * BATCH * HID;
    if (i < N) {
        ((unsigned short*)g_hh)[i] = 0;   // parity-0 slice
        ((unsigned short*)g_hl)[i] = 0;
        ((float*)g_c)[i] = 0.0f;
    }
}

// ==================== kernel 2: precompute P (verified) ====================
__global__ void precompute_P_kernel(
    const float* __restrict__ emb,
    const float* __restrict__ Wgx_f, const float* __restrict__ Wix_f,
    const float* __restrict__ bg_f,  const float* __restrict__ bi_f,
    const float* __restrict__ Wgx_b, const float* __restrict__ Wix_b,
    const float* __restrict__ bg_b,  const float* __restrict__ bi_b)
{
    const int d  = blockIdx.y;
    const int v0 = blockIdx.x * 8;
    const float* __restrict__ Wgx = d ? Wgx_b : Wgx_f;
    const float* __restrict__ Wix = d ? Wix_b : Wix_f;
    const float* __restrict__ bg  = d ? bg_b  : bg_f;
    const float* __restrict__ bi  = d ? bi_b  : bi_f;

    __shared__ float es[8][DIM];
    const int tid = threadIdx.x;
    for (int i = tid; i < 8 * DIM; i += 256)
        es[i >> 8][i & 255] = emb[(v0 + (i >> 8)) * DIM + (i & 255)];
    __syncthreads();

    for (int rep = 0; rep < 8; rep++) {
        const int n = tid + rep * 256;
        const float* __restrict__ W = (n < HID) ? Wgx : Wix;
        const int nn = n & (HID - 1);
        const float bias = (n < HID) ? bg[nn] : bi[nn];
        float acc[8];
        #pragma unroll
        for (int v = 0; v < 8; v++) acc[v] = 0.0f;
        for (int k = 0; k < DIM; k++) {
            const float w = __ldg(&W[k * HID + nn]);
            #pragma unroll
            for (int v = 0; v < 8; v++) acc[v] = fmaf(es[v][k], w, acc[v]);
        }
        #pragma unroll
        for (int v = 0; v < 8; v++) g_P[d][v0 + v][n] = acc[v] + bias;
    }
}

// ==================== kernel 3: transpose + split weights (verified) ====================
__global__ void transpose_split_kernel(
    const float* __restrict__ W0, const float* __restrict__ W1,
    const float* __restrict__ W2, const float* __restrict__ W3)
{
    const int z = blockIdx.z;                 // 0:Wgh_f 1:Wih_f 2:Wgh_b 3:Wih_b
    const float* __restrict__ W = (z == 0) ? W0 : (z == 1) ? W1 : (z == 2) ? W2 : W3;
    const int d = z >> 1, gate = z & 1;
    const int k0 = blockIdx.x * 32, n0 = blockIdx.y * 32;
    const int tx = threadIdx.x, ty = threadIdx.y;

    __shared__ float ts[32][33];
    #pragma unroll
    for (int i = 0; i < 4; i++)
        ts[ty + i * 8][tx] = W[(k0 + ty + i * 8) * HID + n0 + tx];
    __syncthreads();
    #pragma unroll
    for (int i = 0; i < 4; i++) {
        const float v = ts[tx][ty + i * 8];
        const __nv_bfloat16 hi = __float2bfloat16_rn(v);
        const __nv_bfloat16 lo = __float2bfloat16_rn(v - __bfloat162float(hi));
        const int n = gate * HID + n0 + ty + i * 8;
        g_Wt[d][0][n][k0 + tx] = hi;
        g_Wt[d][1][n][k0 + tx] = lo;
    }
}

// ==================== kernel 4: HMMA LSTM step ====================
// grid (16 j, 4 m, 2 dir) = 128 CTAs, 512 threads (16 warps, 2m x 8n of 32x16 tiles).
// Output per CTA: O[64 batch][128] = [g-gate cols j0..j0+63 | i-gate cols].
// 3-term split-bf16 (hi*hi + lo*hi + hi*lo), fp32 register accumulators.
// 3-stage cp.async pipeline, loads issued at iteration top (prefetch distance 2).
__global__ __launch_bounds__(512, 1)
void lstm_step_mma(const int* __restrict__ x, int t)
{
    extern __shared__ char sm_raw[];
    char* smp = (char*)(((uintptr_t)sm_raw + 1023) & ~(uintptr_t)1023);
    const uint32_t smb = smem_u32(smp);

    const int d   = blockIdx.z;
    const int bm0 = blockIdx.y * MT;
    const int j0  = blockIdx.x * NT;
    const int rp  = t & 1;
    const int wp  = rp ^ 1;
    const int tid = threadIdx.x;
    const int wid = tid >> 5, lane = tid & 31;
    const int wm = wid >> 3, wn = wid & 7;       // warp grid 2m x 8n

    const char* srcA0 = (const char*)&g_hh[rp][d][bm0][0];
    const char* srcA1 = (const char*)&g_hl[rp][d][bm0][0];
    const char* srcB0 = (const char*)&g_Wt[d][0][0][0];
    const char* srcB1 = (const char*)&g_Wt[d][1][0][0];

    // ---- chunk loader: 48 KB per stage via cp.async (6 x 16B per thread) ----
    auto load_chunk = [&](int c, int sb) {
        const int kb = c * 128;                  // byte offset along k
        #pragma unroll
        for (int i = 0; i < 2; i++) {            // A hi/lo: 2 x 64 rows x 128 B
            const int idx = tid + i * 512;
            const int hl = idx >> 9, r = (idx >> 3) & 63, ch = idx & 7;
            const uint32_t sa = smb + sb + (hl ? ST_A_LO : ST_A_HI)
                              + r * 128 + ((ch ^ (r & 7)) << 4);
            const char* g = (hl ? srcA1 : srcA0) + r * 2048 + kb + ch * 16;
            cp16(sa, g);
        }
        #pragma unroll
        for (int i = 0; i < 4; i++) {            // B hi/lo: 2 x 128 rows x 128 B
            const int idx = tid + i * 512;
            const int hl = idx >> 10, br = (idx >> 3) & 127, ch = idx & 7;
            const int n = j0 + br + ((br & 64) ? 960 : 0);   // g rows then i rows
            const uint32_t sa = smb + sb + (hl ? ST_B_LO : ST_B_HI)
                              + br * 128 + ((ch ^ (br & 7)) << 4);
            const char* g = (hl ? srcB1 : srcB0) + (size_t)n * 2048 + kb + ch * 16;
            cp16(sa, g);
        }
    };

    float acc[2][2][4];
    #pragma unroll
    for (int mi = 0; mi < 2; mi++)
        #pragma unroll
        for (int ni = 0; ni < 2; ni++)
            #pragma unroll
            for (int e = 0; e < 4; e++) acc[mi][ni][e] = 0.0f;

    load_chunk(0, 0);         CP_COMMIT();
    load_chunk(1, STAGE);     CP_COMMIT();

    for (int c = 0; c < NCHUNK; c++) {
        // prefetch distance 2: issue load for c+2 before computing c.
        // Safe: buf[(c+2)%3] == buf[(c-1)%3], whose compute finished at the
        // barrier that ended iteration c-1.
        if (c + 2 < NCHUNK) load_chunk(c + 2, ((c + 2) % NSTAGE) * STAGE);
        CP_COMMIT();                              // keep group counts aligned
        CP_WAIT2();                               // group c complete (<=2 pending)
        __syncthreads();
        const uint32_t buf = smb + (c % NSTAGE) * STAGE;

        #pragma unroll
        for (int s = 0; s < 4; s++) {            // 4 k16 steps per chunk
            uint32_t ah[2][4], al[2][4], bh[4], bl[4];
            #pragma unroll
            for (int mi = 0; mi < 2; mi++) {
                const int row = wm * 32 + mi * 16 + (lane & 15);
                const int cg  = s * 2 + (lane >> 4);
                const uint32_t a = buf + ST_A_HI + row * 128 + ((cg ^ (row & 7)) << 4);
                ldm4(ah[mi], a);
                ldm4(al[mi], a + (ST_A_LO - ST_A_HI));
            }
            {   // one x4 covers this warp's 16 B-rows (= 16 output cols)
                const int br = wn * 16 + ((lane >> 4) << 3) + (lane & 7);
                const int cg = s * 2 + ((lane >> 3) & 1);
                const uint32_t a = buf + ST_B_HI + br * 128 + ((cg ^ (br & 7)) << 4);
                ldm4(bh, a);
                ldm4(bl, a + (ST_B_LO - ST_B_HI));
            }
            #pragma unroll
            for (int mi = 0; mi < 2; mi++)
                #pragma unroll
                for (int ni = 0; ni < 2; ni++) {
                    mma_bf16(acc[mi][ni], ah[mi], &bh[ni * 2]);   // hi*hi
                    mma_bf16(acc[mi][ni], al[mi], &bh[ni * 2]);   // lo*hi
                    mma_bf16(acc[mi][ni], ah[mi], &bl[ni * 2]);   // hi*lo
                }
        }
        __syncthreads();                          // compute(c) done before anyone
    }                                             // overwrites buf[c%3] (iter c+1)

    // ---- stage accumulators through smem so g and i pair up per (b, j) ----
    float* O = (float*)smp;                       // 64 x OPITCH fp32 (overwrites stage 0)
    #pragma unroll
    for (int mi = 0; mi < 2; mi++)
        #pragma unroll
        for (int ni = 0; ni < 2; ni++) {
            const int r0  = wm * 32 + mi * 16 + (lane >> 2);
            const int col = wn * 16 + ni * 8 + (lane & 3) * 2;
            *(float2*)&O[r0 * OPITCH + col]       = make_float2(acc[mi][ni][0], acc[mi][ni][1]);
            *(float2*)&O[(r0 + 8) * OPITCH + col] = make_float2(acc[mi][ni][2], acc[mi][ni][3]);
        }
    __syncthreads();

    // ---- fused LSTM elementwise update (same math as verified R7/R9) ----
    const int tcol = d ? (SEQ - 2 - t) : t;
    #pragma unroll
    for (int rep = 0; rep < 2; rep++) {
        const int qid = tid + rep * 512;          // 1024 j-quads: 64 b x 16 quads
        const int bl_ = qid >> 4;
        const int jl  = (qid & 15) * 4;
        const int b   = bm0 + bl_;
        const int tok = __ldg(&x[b * SEQ + tcol]);
        const int j   = j0 + jl;

        const float4 ga = *(const float4*)&O[bl_ * OPITCH + jl];
        const float4 ia = *(const float4*)&O[bl_ * OPITCH + 64 + jl];
        const float4 pg = *(const float4*)&g_P[d][tok][j];
        const float4 pi = *(const float4*)&g_P[d][tok][HID + j];
        const float4 co = *(const float4*)&g_c[d][b][j];

        float gv[4], iv[4], cn[4], hn[4];
        gv[0] = tanhf(ga.x + pg.x); gv[1] = tanhf(ga.y + pg.y);
        gv[2] = tanhf(ga.z + pg.z); gv[3] = tanhf(ga.w + pg.w);
        iv[0] = sigmoidf_(ia.x + pi.x); iv[1] = sigmoidf_(ia.y + pi.y);
        iv[2] = sigmoidf_(ia.z + pi.z); iv[3] = sigmoidf_(ia.w + pi.w);

        cn[0] = iv[0] * (gv[0] + co.x);
        cn[1] = iv[1] * (gv[1] + co.y);
        cn[2] = iv[2] * (gv[2] + co.z);
        cn[3] = iv[3] * (gv[3] + co.w);
        *(float4*)&g_c[d][b][j] = make_float4(cn[0], cn[1], cn[2], cn[3]);

        #pragma unroll
        for (int e = 0; e < 4; e++) hn[e] = tanhf(cn[e]) * iv[e];

        __nv_bfloat16 h0 = __float2bfloat16_rn(hn[0]);
        __nv_bfloat16 h1 = __float2bfloat16_rn(hn[1]);
        __nv_bfloat16 h2 = __float2bfloat16_rn(hn[2]);
        __nv_bfloat16 h3 = __float2bfloat16_rn(hn[3]);
        __nv_bfloat162 p01 = __halves2bfloat162(h0, h1);
        __nv_bfloat162 p23 = __halves2bfloat162(h2, h3);
        *(uint32_t*)&g_hh[wp][d][b][j]     = *(uint32_t*)&p01;
        *(uint32_t*)&g_hh[wp][d][b][j + 2] = *(uint32_t*)&p23;
        __nv_bfloat162 l01 = __halves2bfloat162(
            __float2bfloat16_rn(hn[0] - __bfloat162float(h0)),
            __float2bfloat16_rn(hn[1] - __bfloat162float(h1)));
        __nv_bfloat162 l23 = __halves2bfloat162(
            __float2bfloat16_rn(hn[2] - __bfloat162float(h2)),
            __float2bfloat16_rn(hn[3] - __bfloat162float(h3)));
        *(uint32_t*)&g_hl[wp][d][b][j]     = *(uint32_t*)&l01;
        *(uint32_t*)&g_hl[wp][d][b][j + 2] = *(uint32_t*)&l23;
    }
}

// ==================== kernel 5: prediction head ====================
// Final h is in parity 1 (t=510 even: reads 0, writes 1). h = hi + lo.
__global__ void head_kernel(const float* __restrict__ Wp,
                            const float* __restrict__ bp,
                            float* __restrict__ out)
{
    const int b   = blockIdx.x;
    const int tid = threadIdx.x;   // 256
    float acc[NCLS];
    #pragma unroll
    for (int c = 0; c < NCLS; c++) acc[c] = 0.0f;
    for (int j = tid; j < 2 * HID; j += 256) {
        const int dd = (j < HID) ? 0 : 1;
        const int jj = j & (HID - 1);
        const float hv = __bfloat162float(g_hh[1][dd][b][jj]) +
                         __bfloat162float(g_hl[1][dd][b][jj]);
        #pragma unroll
        for (int c = 0; c < NCLS; c++)
            acc[c] = fmaf(hv, __ldg(&Wp[j * NCLS + c]), acc[c]);
    }
    __shared__ float red[8][NCLS];
    #pragma unroll
    for (int c = 0; c < NCLS; c++) {
        float v = acc[c];
        #pragma unroll
        for (int o = 16; o > 0; o >>= 1)
            v += __shfl_down_sync(0xffffffffu, v, o);
        if ((tid & 31) == 0) red[tid >> 5][c] = v;
    }
    __syncthreads();
    if (tid < NCLS) {
        float s = bp[tid];
        #pragma unroll
        for (int w = 0; w < 8; w++) s += red[w][tid];
        out[b * NCLS + tid] = s;
    }
}

// ==================== launch ====================
extern "C" void kernel_launch(void* const* d_in, const int* in_sizes, int n_in,
                              void* d_out, int out_size) {
    const int*   x     = (const int*)  d_in[0];
    const float* emb   = (const float*)d_in[1];
    const float* Wgx_f = (const float*)d_in[2];
    const float* Wgh_f = (const float*)d_in[3];
    const float* bg_f  = (const float*)d_in[4];
    const float* Wix_f = (const float*)d_in[5];
    const float* Wih_f = (const float*)d_in[6];
    const float* bi_f  = (const float*)d_in[7];
    const float* Wgx_b = (const float*)d_in[8];
    const float* Wgh_b = (const float*)d_in[9];
    const float* bg_b  = (const float*)d_in[10];
    const float* Wix_b = (const float*)d_in[11];
    const float* Wih_b = (const float*)d_in[12];
    const float* bi_b  = (const float*)d_in[13];
    const float* Wp    = (const float*)d_in[14];
    const float* bp    = (const float*)d_in[15];
    float* out = (float*)d_out;

    const int DSMEM = NSTAGE * STAGE + 1024;   // 145 KB + alignment slack
    cudaFuncSetAttribute(lstm_step_mma, cudaFuncAttributeMaxDynamicSharedMemorySize, DSMEM);

    zero_state_kernel<<<(2 * BATCH * HID + 511) / 512, 512>>>();
    precompute_P_kernel<<<dim3(VOC / 8, 2), 256>>>(
        emb, Wgx_f, Wix_f, bg_f, bi_f, Wgx_b, Wix_b, bg_b, bi_b);
    transpose_split_kernel<<<dim3(32, 32, 4), dim3(32, 8)>>>(Wgh_f, Wih_f, Wgh_b, Wih_b);

    const dim3 sg(HID / NT, BATCH / MT, 2);   // 16 x 4 x 2 = 128 CTAs
    for (int t = 0; t < NSTEP; t++)
        lstm_step_mma<<<sg, 512, DSMEM>>>(x, t);

    head_kernel<<<BATCH, 256>>>(Wp, bp, out);
}

// round 11
// speedup vs baseline: 1.7176x; 1.7176x over previous
#include <cuda_runtime.h>
#include <cuda_bf16.h>
#include <cstdint>

// Problem dims
#define BATCH 256
#define SEQ   512
#define DIM   256
#define HID   1024
#define NCLS  10
#define NSTEP 511   // SEQ - 1
#define VOC   512

// Step GEMM tiling
#define MT  64            // batch tile
#define NT  64            // j tile (per gate; CTA computes g and i => 128 output cols)
#define KCH 64            // K chunk (64 bf16 = 128 B rows)
#define NCHUNK (HID / KCH)   // 16

// smem stage layout (byte offsets inside one stage)
#define ST_A_HI 0
#define ST_A_LO 8192
#define ST_B_HI 16384
#define ST_B_LO 32768
#define STAGE   49152
#define NSTAGE  4            // 192 KB total; distance-3 prefetch, 1 barrier/chunk
#define OPITCH  132          // fp32 O tile row pitch (floats); 132*4=528 B, 16B-divisible

// -------- device scratch (no allocations allowed) --------
__device__ float g_P[2][VOC][2 * HID];                 // input projections, 8 MB
// transposed+split recurrent weights, gates merged on N: n<1024 -> g, n>=1024 -> i
__device__ __nv_bfloat16 g_Wt[2][2][2048][HID];        // [dir][hi/lo][n][k], 16 MB
__device__ __nv_bfloat16 g_hh[2][2][BATCH][HID];       // h high half [parity][dir][b][k]
__device__ __nv_bfloat16 g_hl[2][2][BATCH][HID];       // h low  half
__device__ float g_c[2][BATCH][HID];                   // cell state fp32

// ==================== PTX helpers (baseline sm_80+ features only) ====================
__device__ __forceinline__ uint32_t smem_u32(const void* p) {
    uint32_t a;
    asm("{ .reg .u64 t; cvta.to.shared.u64 t, %1; cvt.u32.u64 %0, t; }" : "=r"(a) : "l"(p));
    return a;
}
__device__ __forceinline__ void cp16(uint32_t saddr, const void* g) {
    asm volatile("cp.async.cg.shared.global [%0], [%1], 16;" :: "r"(saddr), "l"(g) : "memory");
}
#define CP_COMMIT() asm volatile("cp.async.commit_group;" ::: "memory")
#define CP_WAIT2()  asm volatile("cp.async.wait_group 2;" ::: "memory")

__device__ __forceinline__ void ldm4(uint32_t* r, uint32_t addr) {
    asm volatile("ldmatrix.sync.aligned.m8n8.x4.shared.b16 {%0,%1,%2,%3}, [%4];"
                 : "=r"(r[0]), "=r"(r[1]), "=r"(r[2]), "=r"(r[3]) : "r"(addr));
}
// D(16x8,f32) += A(16x16 row-major bf16) * B(16x8 col-major bf16)
__device__ __forceinline__ void mma_bf16(float* c, const uint32_t* a, const uint32_t* b) {
    asm volatile("mma.sync.aligned.m16n8k16.row.col.f32.bf16.bf16.f32 "
                 "{%0,%1,%2,%3}, {%4,%5,%6,%7}, {%8,%9}, {%0,%1,%2,%3};"
                 : "+f"(c[0]), "+f"(c[1]), "+f"(c[2]), "+f"(c[3])
                 : "r"(a[0]), "r"(a[1]), "r"(a[2]), "r"(a[3]), "r"(b[0]), "r"(b[1]));
}
__device__ __forceinline__ float sigmoidf_(float x) { return 1.0f / (1.0f + __expf(-x)); }

// ==================== kernel 1: zero state ====================
__global__ void zero_state_kernel() {
    int i = blockIdx.x * blockDim.x + threadIdx.x;
    const int N = 2 * BATCH * HID;
    if (i < N) {
        ((unsigned short*)g_hh)[i] = 0;   // parity-0 slice
        ((unsigned short*)g_hl)[i] = 0;
        ((float*)g_c)[i] = 0.0f;
    }
}

// ==================== kernel 2: precompute P (verified) ====================
__global__ void precompute_P_kernel(
    const float* __restrict__ emb,
    const float* __restrict__ Wgx_f, const float* __restrict__ Wix_f,
    const float* __restrict__ bg_f,  const float* __restrict__ bi_f,
    const float* __restrict__ Wgx_b, const float* __restrict__ Wix_b,
    const float* __restrict__ bg_b,  const float* __restrict__ bi_b)
{
    const int d  = blockIdx.y;
    const int v0 = blockIdx.x * 8;
    const float* __restrict__ Wgx = d ? Wgx_b : Wgx_f;
    const float* __restrict__ Wix = d ? Wix_b : Wix_f;
    const float* __restrict__ bg  = d ? bg_b  : bg_f;
    const float* __restrict__ bi  = d ? bi_b  : bi_f;

    __shared__ float es[8][DIM];
    const int tid = threadIdx.x;
    for (int i = tid; i < 8 * DIM; i += 256)
        es[i >> 8][i & 255] = emb[(v0 + (i >> 8)) * DIM + (i & 255)];
    __syncthreads();

    for (int rep = 0; rep < 8; rep++) {
        const int n = tid + rep * 256;
        const float* __restrict__ W = (n < HID) ? Wgx : Wix;
        const int nn = n & (HID - 1);
        const float bias = (n < HID) ? bg[nn] : bi[nn];
        float acc[8];
        #pragma unroll
        for (int v = 0; v < 8; v++) acc[v] = 0.0f;
        for (int k = 0; k < DIM; k++) {
            const float w = __ldg(&W[k * HID + nn]);
            #pragma unroll
            for (int v = 0; v < 8; v++) acc[v] = fmaf(es[v][k], w, acc[v]);
        }
        #pragma unroll
        for (int v = 0; v < 8; v++) g_P[d][v0 + v][n] = acc[v] + bias;
    }
}

// ==================== kernel 3: transpose + split weights (verified) ====================
__global__ void transpose_split_kernel(
    const float* __restrict__ W0, const float* __restrict__ W1,
    const float* __restrict__ W2, const float* __restrict__ W3)
{
    const int z = blockIdx.z;                 // 0:Wgh_f 1:Wih_f 2:Wgh_b 3:Wih_b
    const float* __restrict__ W = (z == 0) ? W0 : (z == 1) ? W1 : (z == 2) ? W2 : W3;
    const int d = z >> 1, gate = z & 1;
    const int k0 = blockIdx.x * 32, n0 = blockIdx.y * 32;
    const int tx = threadIdx.x, ty = threadIdx.y;

    __shared__ float ts[32][33];
    #pragma unroll
    for (int i = 0; i < 4; i++)
        ts[ty + i * 8][tx] = W[(k0 + ty + i * 8) * HID + n0 + tx];
    __syncthreads();
    #pragma unroll
    for (int i = 0; i < 4; i++) {
        const float v = ts[tx][ty + i * 8];
        const __nv_bfloat16 hi = __float2bfloat16_rn(v);
        const __nv_bfloat16 lo = __float2bfloat16_rn(v - __bfloat162float(hi));
        const int n = gate * HID + n0 + ty + i * 8;
        g_Wt[d][0][n][k0 + tx] = hi;
        g_Wt[d][1][n][k0 + tx] = lo;
    }
}

// ==================== kernel 4: HMMA LSTM step ====================
// grid (16 j, 4 m, 2 dir) = 128 CTAs, 256 threads (8 warps, 2m x 4n of 32x32 tiles).
// Output per CTA: O[64 batch][128] = [g-gate cols j0..j0+63 | i-gate cols].
// 3-term split-bf16 (hi*hi + lo*hi + hi*lo), fp32 register accumulators.
// 4-stage cp.async pipeline (prefetch distance 3), ONE barrier per chunk,
// double-buffered register fragments across the 4 k16 sub-steps.
__global__ __launch_bounds__(256, 1)
void lstm_step_mma(const int* __restrict__ x, int t)
{
    extern __shared__ char sm_raw[];
    char* smp = (char*)(((uintptr_t)sm_raw + 1023) & ~(uintptr_t)1023);
    const uint32_t smb = smem_u32(smp);

    const int d   = blockIdx.z;
    const int bm0 = blockIdx.y * MT;
    const int j0  = blockIdx.x * NT;
    const int rp  = t & 1;
    const int wp  = rp ^ 1;
    const int tid = threadIdx.x;
    const int wid = tid >> 5, lane = tid & 31;
    const int wm = wid >> 2, wn = wid & 3;       // warp grid 2m x 4n

    const char* srcA0 = (const char*)&g_hh[rp][d][bm0][0];
    const char* srcA1 = (const char*)&g_hl[rp][d][bm0][0];
    const char* srcB0 = (const char*)&g_Wt[d][0][0][0];
    const char* srcB1 = (const char*)&g_Wt[d][1][0][0];

    // ---- chunk loader: 48 KB per stage via cp.async (12 x 16B per thread) ----
    auto load_chunk = [&](int c, int sb) {
        const int kb = c * 128;                  // byte offset along k
        #pragma unroll
        for (int i = 0; i < 4; i++) {            // A hi/lo: 2 x 64 rows x 128 B
            const int idx = tid + i * 256;
            const int hl = idx >> 9, r = (idx >> 3) & 63, ch = idx & 7;
            const uint32_t sa = smb + sb + (hl ? ST_A_LO : ST_A_HI)
                              + r * 128 + ((ch ^ (r & 7)) << 4);
            const char* g = (hl ? srcA1 : srcA0) + r * 2048 + kb + ch * 16;
            cp16(sa, g);
        }
        #pragma unroll
        for (int i = 0; i < 8; i++) {            // B hi/lo: 2 x 128 rows x 128 B
            const int idx = tid + i * 256;
            const int hl = idx >> 10, br = (idx >> 3) & 127, ch = idx & 7;
            const int n = j0 + br + ((br & 64) ? 960 : 0);   // g rows then i rows
            const uint32_t sa = smb + sb + (hl ? ST_B_LO : ST_B_HI)
                              + br * 128 + ((ch ^ (br & 7)) << 4);
            const char* g = (hl ? srcB1 : srcB0) + (size_t)n * 2048 + kb + ch * 16;
            cp16(sa, g);
        }
    };

    float acc[2][4][4];
    #pragma unroll
    for (int mi = 0; mi < 2; mi++)
        #pragma unroll
        for (int ni = 0; ni < 4; ni++)
            #pragma unroll
            for (int e = 0; e < 4; e++) acc[mi][ni][e] = 0.0f;

    // double-buffered register fragments
    uint32_t ah[2][2][4], al[2][2][4], bh[2][2][4], bl[2][2][4];
    auto load_frags = [&](uint32_t buf, int s, int q) {
        #pragma unroll
        for (int mi = 0; mi < 2; mi++) {
            const int row = wm * 32 + mi * 16 + (lane & 15);
            const int cg  = s * 2 + (lane >> 4);
            const uint32_t a = buf + ST_A_HI + row * 128 + ((cg ^ (row & 7)) << 4);
            ldm4(ah[q][mi], a);
            ldm4(al[q][mi], a + (ST_A_LO - ST_A_HI));
        }
        #pragma unroll
        for (int p = 0; p < 2; p++) {            // each x4 covers two 8-col n-tiles
            const int br = wn * 32 + p * 16 + ((lane >> 4) << 3) + (lane & 7);
            const int cg = s * 2 + ((lane >> 3) & 1);
            const uint32_t a = buf + ST_B_HI + br * 128 + ((cg ^ (br & 7)) << 4);
            ldm4(bh[q][p], a);
            ldm4(bl[q][p], a + (ST_B_LO - ST_B_HI));
        }
    };

    load_chunk(0, 0);         CP_COMMIT();
    load_chunk(1, STAGE);     CP_COMMIT();
    load_chunk(2, 2 * STAGE); CP_COMMIT();

    for (int c = 0; c < NCHUNK; c++) {
        CP_WAIT2();                               // chunk c landed (<=2 groups pending)
        __syncthreads();                          // all see stage c; also proves
                                                  // compute(c-1) done in all threads
        // distance-3 prefetch into stage (c+3)%4, computed at iter c-2 -> free.
        // (issued AFTER the barrier, so no thread still reads stage (c-1)%4
        //  ... it targets (c+3)%4 == (c-1)%4 only mod 4; safe per barrier above)
        if (c + 3 < NCHUNK) load_chunk(c + 3, ((c + 3) & 3) * STAGE);
        CP_COMMIT();                              // keep group counts aligned

        const uint32_t buf = smb + (c & 3) * STAGE;
        load_frags(buf, 0, 0);
        #pragma unroll
        for (int s = 0; s < 4; s++) {            // 4 k16 steps, reg double-buffer
            const int cur = s & 1;
            if (s < 3) load_frags(buf, s + 1, cur ^ 1);
            #pragma unroll
            for (int mi = 0; mi < 2; mi++)
                #pragma unroll
                for (int ni = 0; ni < 4; ni++) {
                    const uint32_t* bhp = &bh[cur][ni >> 1][(ni & 1) * 2];
                    const uint32_t* blp = &bl[cur][ni >> 1][(ni & 1) * 2];
                    mma_bf16(acc[mi][ni], ah[cur][mi], bhp);   // hi*hi
                    mma_bf16(acc[mi][ni], al[cur][mi], bhp);   // lo*hi
                    mma_bf16(acc[mi][ni], ah[cur][mi], blp);   // hi*lo
                }
        }
        // no trailing barrier: next iteration's top barrier provides the
        // write-after-read guard (stage written at iter c+1 was computed c-1).
    }

    // ---- stage accumulators through smem so g and i pair up per (b, j) ----
    // O tile lives in stage 0; last read of stage 0 was chunk 12, and every
    // thread passed the iter-15 barrier since, so it is free.
    float* O = (float*)smp;                       // 64 x OPITCH fp32
    #pragma unroll
    for (int mi = 0; mi < 2; mi++)
        #pragma unroll
        for (int ni = 0; ni < 4; ni++) {
            const int r0  = wm * 32 + mi * 16 + (lane >> 2);
            const int col = wn * 32 + ni * 8 + (lane & 3) * 2;
            *(float2*)&O[r0 * OPITCH + col]       = make_float2(acc[mi][ni][0], acc[mi][ni][1]);
            *(float2*)&O[(r0 + 8) * OPITCH + col] = make_float2(acc[mi][ni][2], acc[mi][ni][3]);
        }
    __syncthreads();

    // ---- fused LSTM elementwise update (same math as verified R7/R9) ----
    const int tcol = d ? (SEQ - 2 - t) : t;
    #pragma unroll
    for (int rep = 0; rep < 4; rep++) {
        const int qid = tid + rep * 256;          // 1024 j-quads: 64 b x 16 quads
        const int bl_ = qid >> 4;
        const int jl  = (qid & 15) * 4;
        const int b   = bm0 + bl_;
        const int tok = __ldg(&x[b * SEQ + tcol]);
        const int j   = j0 + jl;

        const float4 ga = *(const float4*)&O[bl_ * OPITCH + jl];
        const float4 ia = *(const float4*)&O[bl_ * OPITCH + 64 + jl];
        const float4 pg = *(const float4*)&g_P[d][tok][j];
        const float4 pi = *(const float4*)&g_P[d][tok][HID + j];
        const float4 co = *(const float4*)&g_c[d][b][j];

        float gv[4], iv[4], cn[4], hn[4];
        gv[0] = tanhf(ga.x + pg.x); gv[1] = tanhf(ga.y + pg.y);
        gv[2] = tanhf(ga.z + pg.z); gv[3] = tanhf(ga.w + pg.w);
        iv[0] = sigmoidf_(ia.x + pi.x); iv[1] = sigmoidf_(ia.y + pi.y);
        iv[2] = sigmoidf_(ia.z + pi.z); iv[3] = sigmoidf_(ia.w + pi.w);

        cn[0] = iv[0] * (gv[0] + co.x);
        cn[1] = iv[1] * (gv[1] + co.y);
        cn[2] = iv[2] * (gv[2] + co.z);
        cn[3] = iv[3] * (gv[3] + co.w);
        *(float4*)&g_c[d][b][j] = make_float4(cn[0], cn[1], cn[2], cn[3]);

        #pragma unroll
        for (int e = 0; e < 4; e++) hn[e] = tanhf(cn[e]) * iv[e];

        __nv_bfloat16 h0 = __float2bfloat16_rn(hn[0]);
        __nv_bfloat16 h1 = __float2bfloat16_rn(hn[1]);
        __nv_bfloat16 h2 = __float2bfloat16_rn(hn[2]);
        __nv_bfloat16 h3 = __float2bfloat16_rn(hn[3]);
        __nv_bfloat162 p01 = __halves2bfloat162(h0, h1);
        __nv_bfloat162 p23 = __halves2bfloat162(h2, h3);
        *(uint32_t*)&g_hh[wp][d][b][j]     = *(uint32_t*)&p01;
        *(uint32_t*)&g_hh[wp][d][b][j + 2] = *(uint32_t*)&p23;
        __nv_bfloat162 l01 = __halves2bfloat162(
            __float2bfloat16_rn(hn[0] - __bfloat162float(h0)),
            __float2bfloat16_rn(hn[1] - __bfloat162float(h1)));
        __nv_bfloat162 l23 = __halves2bfloat162(
            __float2bfloat16_rn(hn[2] - __bfloat162float(h2)),
            __float2bfloat16_rn(hn[3] - __bfloat162float(h3)));
        *(uint32_t*)&g_hl[wp][d][b][j]     = *(uint32_t*)&l01;
        *(uint32_t*)&g_hl[wp][d][b][j + 2] = *(uint32_t*)&l23;
    }
}

// ==================== kernel 5: prediction head ====================
// Final h is in parity 1 (t=510 even: reads 0, writes 1). h = hi + lo.
__global__ void head_kernel(const float* __restrict__ Wp,
                            const float* __restrict__ bp,
                            float* __restrict__ out)
{
    const int b   = blockIdx.x;
    const int tid = threadIdx.x;   // 256
    float acc[NCLS];
    #pragma unroll
    for (int c = 0; c < NCLS; c++) acc[c] = 0.0f;
    for (int j = tid; j < 2 * HID; j += 256) {
        const int dd = (j < HID) ? 0 : 1;
        const int jj = j & (HID - 1);
        const float hv = __bfloat162float(g_hh[1][dd][b][jj]) +
                         __bfloat162float(g_hl[1][dd][b][jj]);
        #pragma unroll
        for (int c = 0; c < NCLS; c++)
            acc[c] = fmaf(hv, __ldg(&Wp[j * NCLS + c]), acc[c]);
    }
    __shared__ float red[8][NCLS];
    #pragma unroll
    for (int c = 0; c < NCLS; c++) {
        float v = acc[c];
        #pragma unroll
        for (int o = 16; o > 0; o >>= 1)
            v += __shfl_down_sync(0xffffffffu, v, o);
        if ((tid & 31) == 0) red[tid >> 5][c] = v;
    }
    __syncthreads();
    if (tid < NCLS) {
        float s = bp[tid];
        #pragma unroll
        for (int w = 0; w < 8; w++) s += red[w][tid];
        out[b * NCLS + tid] = s;
    }
}

// ==================== launch ====================
extern "C" void kernel_launch(void* const* d_in, const int* in_sizes, int n_in,
                              void* d_out, int out_size) {
    const int*   x     = (const int*)  d_in[0];
    const float* emb   = (const float*)d_in[1];
    const float* Wgx_f = (const float*)d_in[2];
    const float* Wgh_f = (const float*)d_in[3];
    const float* bg_f  = (const float*)d_in[4];
    const float* Wix_f = (const float*)d_in[5];
    const float* Wih_f = (const float*)d_in[6];
    const float* bi_f  = (const float*)d_in[7];
    const float* Wgx_b = (const float*)d_in[8];
    const float* Wgh_b = (const float*)d_in[9];
    const float* bg_b  = (const float*)d_in[10];
    const float* Wix_b = (const float*)d_in[11];
    const float* Wih_b = (const float*)d_in[12];
    const float* bi_b  = (const float*)d_in[13];
    const float* Wp    = (const float*)d_in[14];
    const float* bp    = (const float*)d_in[15];
    float* out = (float*)d_out;

    const int DSMEM = NSTAGE * STAGE + 1024;   // 193 KB + alignment slack
    cudaFuncSetAttribute(lstm_step_mma, cudaFuncAttributeMaxDynamicSharedMemorySize, DSMEM);

    zero_state_kernel<<<(2 * BATCH * HID + 511) / 512, 512>>>();
    precompute_P_kernel<<<dim3(VOC / 8, 2), 256>>>(
        emb, Wgx_f, Wix_f, bg_f, bi_f, Wgx_b, Wix_b, bg_b, bi_b);
    transpose_split_kernel<<<dim3(32, 32, 4), dim3(32, 8)>>>(Wgh_f, Wih_f, Wgh_b, Wih_b);

    const dim3 sg(HID / NT, BATCH / MT, 2);   // 16 x 4 x 2 = 128 CTAs
    for (int t = 0; t < NSTEP; t++)
        lstm_step_mma<<<sg, 256, DSMEM>>>(x, t);

    head_kernel<<<BATCH, 256>>>(Wp, bp, out);
}

// round 12
// speedup vs baseline: 3.0986x; 1.8040x over previous
#include <cuda_runtime.h>
#include <cuda_bf16.h>
#include <cuda_fp16.h>
#include <cstdint>

// Problem dims
#define BATCH 256
#define SEQ   512
#define DIM   256
#define HID   1024
#define NCLS  10
#define NSTEP 511   // SEQ - 1
#define VOC   512

// Step GEMM tiling
#define MT  64            // batch tile
#define NT  64            // j tile (per gate; CTA computes g and i => 128 output cols)
#define KCH 64            // K chunk (64 fp16 = 128 B rows)
#define NCHUNK (HID / KCH)   // 16

// smem stage layout (byte offsets inside one stage)
#define ST_A  0              // A: 64 rows x 128 B = 8 KB
#define ST_B  8192           // B: 128 rows x 128 B = 16 KB
#define STAGE 24576
#define NSTAGE 4             // 96 KB; distance-3 prefetch, 1 barrier/chunk
#define OPITCH 132           // fp32 O tile row pitch (floats)

// -------- device scratch (no allocations allowed) --------
__device__ float g_P[2][VOC][2 * HID];                 // input projections, 8 MB
// transposed fp16 recurrent weights, gates merged on N: n<1024 -> g, n>=1024 -> i
__device__ __half g_Wt[2][2048][HID];                  // [dir][n][k], 8 MB
__device__ __half g_h[2][2][BATCH][HID];               // h fp16 [parity][dir][b][k], 2 MB
__device__ float g_c[2][BATCH][HID];                   // cell state fp32

// ==================== PTX helpers (baseline sm_80+ features only) ====================
__device__ __forceinline__ uint32_t smem_u32(const void* p) {
    uint32_t a;
    asm("{ .reg .u64 t; cvta.to.shared.u64 t, %1; cvt.u32.u64 %0, t; }" : "=r"(a) : "l"(p));
    return a;
}
__device__ __forceinline__ void cp16(uint32_t saddr, const void* g) {
    asm volatile("cp.async.cg.shared.global [%0], [%1], 16;" :: "r"(saddr), "l"(g) : "memory");
}
#define CP_COMMIT() asm volatile("cp.async.commit_group;" ::: "memory")
#define CP_WAIT2()  asm volatile("cp.async.wait_group 2;" ::: "memory")

__device__ __forceinline__ void ldm4(uint32_t* r, uint32_t addr) {
    asm volatile("ldmatrix.sync.aligned.m8n8.x4.shared.b16 {%0,%1,%2,%3}, [%4];"
                 : "=r"(r[0]), "=r"(r[1]), "=r"(r[2]), "=r"(r[3]) : "r"(addr));
}
// D(16x8,f32) += A(16x16 row-major fp16) * B(16x8 col-major fp16)
__device__ __forceinline__ void mma_f16(float* c, const uint32_t* a, const uint32_t* b) {
    asm volatile("mma.sync.aligned.m16n8k16.row.col.f32.f16.f16.f32 "
                 "{%0,%1,%2,%3}, {%4,%5,%6,%7}, {%8,%9}, {%0,%1,%2,%3};"
                 : "+f"(c[0]), "+f"(c[1]), "+f"(c[2]), "+f"(c[3])
                 : "r"(a[0]), "r"(a[1]), "r"(a[2]), "r"(a[3]), "r"(b[0]), "r"(b[1]));
}
__device__ __forceinline__ float sigmoidf_(float x) { return 1.0f / (1.0f + __expf(-x)); }

// ==================== kernel 1: zero state ====================
__global__ void zero_state_kernel() {
    int i = blockIdx.x * blockDim.x + threadIdx.x;
    const int N = 2 * BATCH * HID;   // parity-0 slice of g_h; same count for g_c
    if (i < N) {
        ((unsigned short*)g_h)[i] = 0;
        ((float*)g_c)[i] = 0.0f;
    }
}

// ==================== kernel 2: precompute P (verified) ====================
__global__ void precompute_P_kernel(
    const float* __restrict__ emb,
    const float* __restrict__ Wgx_f, const float* __restrict__ Wix_f,
    const float* __restrict__ bg_f,  const float* __restrict__ bi_f,
    const float* __restrict__ Wgx_b, const float* __restrict__ Wix_b,
    const float* __restrict__ bg_b,  const float* __restrict__ bi_b)
{
    const int d  = blockIdx.y;
    const int v0 = blockIdx.x * 8;
    const float* __restrict__ Wgx = d ? Wgx_b : Wgx_f;
    const float* __restrict__ Wix = d ? Wix_b : Wix_f;
    const float* __restrict__ bg  = d ? bg_b  : bg_f;
    const float* __restrict__ bi  = d ? bi_b  : bi_f;

    __shared__ float es[8][DIM];
    const int tid = threadIdx.x;
    for (int i = tid; i < 8 * DIM; i += 256)
        es[i >> 8][i & 255] = emb[(v0 + (i >> 8)) * DIM + (i & 255)];
    __syncthreads();

    for (int rep = 0; rep < 8; rep++) {
        const int n = tid + rep * 256;
        const float* __restrict__ W = (n < HID) ? Wgx : Wix;
        const int nn = n & (HID - 1);
        const float bias = (n < HID) ? bg[nn] : bi[nn];
        float acc[8];
        #pragma unroll
        for (int v = 0; v < 8; v++) acc[v] = 0.0f;
        for (int k = 0; k < DIM; k++) {
            const float w = __ldg(&W[k * HID + nn]);
            #pragma unroll
            for (int v = 0; v < 8; v++) acc[v] = fmaf(es[v][k], w, acc[v]);
        }
        #pragma unroll
        for (int v = 0; v < 8; v++) g_P[d][v0 + v][n] = acc[v] + bias;
    }
}

// ==================== kernel 3: transpose weights to fp16 ====================
// W[k][n] fp32 -> g_Wt[d][gate*1024+n][k] fp16. grid (32,32,4), block (32,8)
__global__ void transpose_half_kernel(
    const float* __restrict__ W0, const float* __restrict__ W1,
    const float* __restrict__ W2, const float* __restrict__ W3)
{
    const int z = blockIdx.z;                 // 0:Wgh_f 1:Wih_f 2:Wgh_b 3:Wih_b
    const float* __restrict__ W = (z == 0) ? W0 : (z == 1) ? W1 : (z == 2) ? W2 : W3;
    const int d = z >> 1, gate = z & 1;
    const int k0 = blockIdx.x * 32, n0 = blockIdx.y * 32;
    const int tx = threadIdx.x, ty = threadIdx.y;

    __shared__ float ts[32][33];
    #pragma unroll
    for (int i = 0; i < 4; i++)
        ts[ty + i * 8][tx] = W[(k0 + ty + i * 8) * HID + n0 + tx];
    __syncthreads();
    #pragma unroll
    for (int i = 0; i < 4; i++) {
        const int n = gate * HID + n0 + ty + i * 8;
        g_Wt[d][n][k0 + tx] = __float2half_rn(ts[tx][ty + i * 8]);
    }
}

// ==================== kernel 4: fp16 HMMA LSTM step ====================
// grid (16 j, 4 m, 2 dir) = 128 CTAs, 256 threads (8 warps, 2m x 4n of 32x32 tiles).
// Output per CTA: O[64 batch][128] = [g-gate cols j0..j0+63 | i-gate cols].
// Pure fp16 operands, fp32 register accumulators (error budget analysis: ~1e-4 final).
// 4-stage cp.async pipeline (prefetch distance 3), ONE barrier per chunk,
// double-buffered register fragments across the 4 k16 sub-steps.
__global__ __launch_bounds__(256, 1)
void lstm_step_mma(const int* __restrict__ x, int t)
{
    extern __shared__ char sm_raw[];
    char* smp = (char*)(((uintptr_t)sm_raw + 1023) & ~(uintptr_t)1023);
    const uint32_t smb = smem_u32(smp);

    const int d   = blockIdx.z;
    const int bm0 = blockIdx.y * MT;
    const int j0  = blockIdx.x * NT;
    const int rp  = t & 1;
    const int wp  = rp ^ 1;
    const int tid = threadIdx.x;
    const int wid = tid >> 5, lane = tid & 31;
    const int wm = wid >> 2, wn = wid & 3;       // warp grid 2m x 4n

    const char* srcA = (const char*)&g_h[rp][d][bm0][0];
    const char* srcB = (const char*)&g_Wt[d][0][0];

    // ---- chunk loader: 24 KB per stage via cp.async (6 x 16B per thread) ----
    auto load_chunk = [&](int c, int sb) {
        const int kb = c * 128;                  // byte offset along k (64 fp16)
        #pragma unroll
        for (int i = 0; i < 2; i++) {            // A: 64 rows x 128 B
            const int idx = tid + i * 256;
            const int r = idx >> 3, ch = idx & 7;
            const uint32_t sa = smb + sb + ST_A + r * 128 + ((ch ^ (r & 7)) << 4);
            cp16(sa, srcA + r * 2048 + kb + ch * 16);
        }
        #pragma unroll
        for (int i = 0; i < 4; i++) {            // B: 128 rows x 128 B
            const int idx = tid + i * 256;
            const int br = idx >> 3, ch = idx & 7;
            const int n = j0 + br + ((br & 64) ? 960 : 0);   // g rows then i rows
            const uint32_t sa = smb + sb + ST_B + br * 128 + ((ch ^ (br & 7)) << 4);
            cp16(sa, srcB + (size_t)n * 2048 + kb + ch * 16);
        }
    };

    float acc[2][4][4];
    #pragma unroll
    for (int mi = 0; mi < 2; mi++)
        #pragma unroll
        for (int ni = 0; ni < 4; ni++)
            #pragma unroll
            for (int e = 0; e < 4; e++) acc[mi][ni][e] = 0.0f;

    // double-buffered register fragments
    uint32_t ah[2][2][4], bh[2][2][4];
    auto load_frags = [&](uint32_t buf, int s, int q) {
        #pragma unroll
        for (int mi = 0; mi < 2; mi++) {
            const int row = wm * 32 + mi * 16 + (lane & 15);
            const int cg  = s * 2 + (lane >> 4);
            ldm4(ah[q][mi], buf + ST_A + row * 128 + ((cg ^ (row & 7)) << 4));
        }
        #pragma unroll
        for (int p = 0; p < 2; p++) {            // each x4 covers two 8-col n-tiles
            const int br = wn * 32 + p * 16 + ((lane >> 4) << 3) + (lane & 7);
            const int cg = s * 2 + ((lane >> 3) & 1);
            ldm4(bh[q][p], buf + ST_B + br * 128 + ((cg ^ (br & 7)) << 4));
        }
    };

    load_chunk(0, 0);         CP_COMMIT();
    load_chunk(1, STAGE);     CP_COMMIT();
    load_chunk(2, 2 * STAGE); CP_COMMIT();

    for (int c = 0; c < NCHUNK; c++) {
        CP_WAIT2();                               // chunk c landed (<=2 groups pending)
        __syncthreads();                          // all see stage c; proves compute(c-1)
                                                  // finished in every thread
        if (c + 3 < NCHUNK) load_chunk(c + 3, ((c + 3) & 3) * STAGE);
        CP_COMMIT();                              // keep group counts aligned

        const uint32_t buf = smb + (c & 3) * STAGE;
        load_frags(buf, 0, 0);
        #pragma unroll
        for (int s = 0; s < 4; s++) {            // 4 k16 steps, reg double-buffer
            const int cur = s & 1;
            if (s < 3) load_frags(buf, s + 1, cur ^ 1);
            #pragma unroll
            for (int mi = 0; mi < 2; mi++)
                #pragma unroll
                for (int ni = 0; ni < 4; ni++)
                    mma_f16(acc[mi][ni], ah[cur][mi], &bh[cur][ni >> 1][(ni & 1) * 2]);
        }
        // no trailing barrier: next iteration's top barrier provides the
        // write-after-read guard (stage written at iter c+1 was computed at c-1).
    }

    // ---- stage accumulators through smem so g and i pair up per (b, j) ----
    float* O = (float*)smp;                       // 64 x OPITCH fp32 (34 KB < 2 stages)
    #pragma unroll
    for (int mi = 0; mi < 2; mi++)
        #pragma unroll
        for (int ni = 0; ni < 4; ni++) {
            const int r0  = wm * 32 + mi * 16 + (lane >> 2);
            const int col = wn * 32 + ni * 8 + (lane & 3) * 2;
            *(float2*)&O[r0 * OPITCH + col]       = make_float2(acc[mi][ni][0], acc[mi][ni][1]);
            *(float2*)&O[(r0 + 8) * OPITCH + col] = make_float2(acc[mi][ni][2], acc[mi][ni][3]);
        }
    __syncthreads();

    // ---- fused LSTM elementwise update (same math as verified R7/R9/R11) ----
    const int tcol = d ? (SEQ - 2 - t) : t;
    #pragma unroll
    for (int rep = 0; rep < 4; rep++) {
        const int qid = tid + rep * 256;          // 1024 j-quads: 64 b x 16 quads
        const int bl_ = qid >> 4;
        const int jl  = (qid & 15) * 4;
        const int b   = bm0 + bl_;
        const int tok = __ldg(&x[b * SEQ + tcol]);
        const int j   = j0 + jl;

        const float4 ga = *(const float4*)&O[bl_ * OPITCH + jl];
        const float4 ia = *(const float4*)&O[bl_ * OPITCH + 64 + jl];
        const float4 pg = *(const float4*)&g_P[d][tok][j];
        const float4 pi = *(const float4*)&g_P[d][tok][HID + j];
        const float4 co = *(const float4*)&g_c[d][b][j];

        float gv[4], iv[4], cn[4], hn[4];
        gv[0] = tanhf(ga.x + pg.x); gv[1] = tanhf(ga.y + pg.y);
        gv[2] = tanhf(ga.z + pg.z); gv[3] = tanhf(ga.w + pg.w);
        iv[0] = sigmoidf_(ia.x + pi.x); iv[1] = sigmoidf_(ia.y + pi.y);
        iv[2] = sigmoidf_(ia.z + pi.z); iv[3] = sigmoidf_(ia.w + pi.w);

        cn[0] = iv[0] * (gv[0] + co.x);
        cn[1] = iv[1] * (gv[1] + co.y);
        cn[2] = iv[2] * (gv[2] + co.z);
        cn[3] = iv[3] * (gv[3] + co.w);
        *(float4*)&g_c[d][b][j] = make_float4(cn[0], cn[1], cn[2], cn[3]);

        #pragma unroll
        for (int e = 0; e < 4; e++) hn[e] = tanhf(cn[e]) * iv[e];

        __half2 h01 = __floats2half2_rn(hn[0], hn[1]);
        __half2 h23 = __floats2half2_rn(hn[2], hn[3]);
        *(uint32_t*)&g_h[wp][d][b][j]     = *(uint32_t*)&h01;
        *(uint32_t*)&g_h[wp][d][b][j + 2] = *(uint32_t*)&h23;
    }
}

// ==================== kernel 5: prediction head ====================
// Final h is in parity 1 (t=510 even: reads 0, writes 1).
__global__ void head_kernel(const float* __restrict__ Wp,
                            const float* __restrict__ bp,
                            float* __restrict__ out)
{
    const int b   = blockIdx.x;
    const int tid = threadIdx.x;   // 256
    float acc[NCLS];
    #pragma unroll
    for (int c = 0; c < NCLS; c++) acc[c] = 0.0f;
    for (int j = tid; j < 2 * HID; j += 256) {
        const int dd = (j < HID) ? 0 : 1;
        const int jj = j & (HID - 1);
        const float hv = __half2float(g_h[1][dd][b][jj]);
        #pragma unroll
        for (int c = 0; c < NCLS; c++)
            acc[c] = fmaf(hv, __ldg(&Wp[j * NCLS + c]), acc[c]);
    }
    __shared__ float red[8][NCLS];
    #pragma unroll
    for (int c = 0; c < NCLS; c++) {
        float v = acc[c];
        #pragma unroll
        for (int o = 16; o > 0; o >>= 1)
            v += __shfl_down_sync(0xffffffffu, v, o);
        if ((tid & 31) == 0) red[tid >> 5][c] = v;
    }
    __syncthreads();
    if (tid < NCLS) {
        float s = bp[tid];
        #pragma unroll
        for (int w = 0; w < 8; w++) s += red[w][tid];
        out[b * NCLS + tid] = s;
    }
}

// ==================== launch ====================
extern "C" void kernel_launch(void* const* d_in, const int* in_sizes, int n_in,
                              void* d_out, int out_size) {
    const int*   x     = (const int*)  d_in[0];
    const float* emb   = (const float*)d_in[1];
    const float* Wgx_f = (const float*)d_in[2];
    const float* Wgh_f = (const float*)d_in[3];
    const float* bg_f  = (const float*)d_in[4];
    const float* Wix_f = (const float*)d_in[5];
    const float* Wih_f = (const float*)d_in[6];
    const float* bi_f  = (const float*)d_in[7];
    const float* Wgx_b = (const float*)d_in[8];
    const float* Wgh_b = (const float*)d_in[9];
    const float* bg_b  = (const float*)d_in[10];
    const float* Wix_b = (const float*)d_in[11];
    const float* Wih_b = (const float*)d_in[12];
    const float* bi_b  = (const float*)d_in[13];
    const float* Wp    = (const float*)d_in[14];
    const float* bp    = (const float*)d_in[15];
    float* out = (float*)d_out;

    const int DSMEM = NSTAGE * STAGE + 1024;   // 97 KB + alignment slack
    cudaFuncSetAttribute(lstm_step_mma, cudaFuncAttributeMaxDynamicSharedMemorySize, DSMEM);

    zero_state_kernel<<<(2 * BATCH * HID + 511) / 512, 512>>>();
    precompute_P_kernel<<<dim3(VOC / 8, 2), 256>>>(
        emb, Wgx_f, Wix_f, bg_f, bi_f, Wgx_b, Wix_b, bg_b, bi_b);
    transpose_half_kernel<<<dim3(32, 32, 4), dim3(32, 8)>>>(Wgh_f, Wih_f, Wgh_b, Wih_b);

    const dim3 sg(HID / NT, BATCH / MT, 2);   // 16 x 4 x 2 = 128 CTAs
    for (int t = 0; t < NSTEP; t++)
        lstm_step_mma<<<sg, 256, DSMEM>>>(x, t);

    head_kernel<<<BATCH, 256>>>(Wp, bp, out);
}